// round 7
// baseline (speedup 1.0000x reference)
#include <cuda_runtime.h>

// Banded DTW (Sakoe-Chiba w=1) as a min-plus (tropical) 3x3 matrix reduction,
// single fused kernel, last-block-done with MINIMAL sync footprint:
//   - only 32 blocks -> 32-way ticket-atomic contention instead of 128
//   - final cross-block reduce is a single-warp shuffle tree (no smem, no bar)
//
// Row recurrence (costs a=|o_i-t_{i-2}|, b=|o_i-t_{i-1}|, c=|o_i-t_i|;
// a=INF at i=1, c=INF at i=n):
//   n0 = a + min(p0,p1); n1 = b + min(n0,min(p1,p2)); n2 = c + min(n1,p2)
// Min-plus linear -> ordered reduction of 3x3 tropical matrices.
// Answer = M_total[1][1].

#define NTHREADS 512
#define NBLOCKS  32
#define NWARPS   (NTHREADS / 32)

__device__ float g_bmats[NBLOCKS * 9];
__device__ unsigned int g_ticket = 0;

__device__ __forceinline__ float finf() { return __int_as_float(0x7f800000); }

struct Mat { float m[9]; };  // row-major

__device__ __forceinline__ Mat mp_identity() {
    const float INF = finf();
    Mat M;
    M.m[0] = 0.f; M.m[1] = INF; M.m[2] = INF;
    M.m[3] = INF; M.m[4] = 0.f; M.m[5] = INF;
    M.m[6] = INF; M.m[7] = INF; M.m[8] = 0.f;
    return M;
}

// C = L o E (E earlier, L later): C[i][j] = min_k L[i][k] + E[k][j]
__device__ __forceinline__ Mat mp_combine(const Mat& L, const Mat& E) {
    Mat C;
#pragma unroll
    for (int i = 0; i < 3; ++i) {
#pragma unroll
        for (int j = 0; j < 3; ++j) {
            float v = L.m[i * 3 + 0] + E.m[0 + j];
            v = fminf(v, L.m[i * 3 + 1] + E.m[3 + j]);
            v = fminf(v, L.m[i * 3 + 2] + E.m[6 + j]);
            C.m[i * 3 + j] = v;
        }
    }
    return C;
}

// One DTW row-step applied to all three columns of M.
__device__ __forceinline__ void step_cols(Mat& M, float a, float b, float c) {
#pragma unroll
    for (int j = 0; j < 3; ++j) {
        float p0 = M.m[0 + j], p1 = M.m[3 + j], p2 = M.m[6 + j];
        float n0 = a + fminf(p0, p1);
        float n1 = b + fminf(n0, fminf(p1, p2));
        float n2 = c + fminf(n1, p2);
        M.m[0 + j] = n0; M.m[3 + j] = n1; M.m[6 + j] = n2;
    }
}

// Order-preserving in-warp tree over `levels` shuffle stages.
// Lane t holds segment t (ascending = later). Result lands in lane 0.
template <int LEVELS>
__device__ __forceinline__ void warp_reduce_mat(Mat& M, int lane) {
#pragma unroll
    for (int s = 1; s < (1 << LEVELS); s <<= 1) {
        Mat other;
#pragma unroll
        for (int q = 0; q < 9; ++q)
            other.m[q] = __shfl_down_sync(0xffffffffu, M.m[q], s);
        if ((lane & (2 * s - 1)) == 0) M = mp_combine(other, M);
    }
}

__global__ void __launch_bounds__(NTHREADS) dtw_fused(
    const float* __restrict__ oseq, const float* __restrict__ tgt,
    int n, int chunk, float* __restrict__ out) {
    const float INF = finf();
    const int tid = threadIdx.x;
    const int lane = tid & 31;
    const int warp = tid >> 5;
    const int gid = blockIdx.x * NTHREADS + tid;
    const long s0 = (long)gid * chunk;  // first step is i = s0 + 1 (1-based)

    Mat M = mp_identity();

    if (chunk == 8 && s0 + 8 <= n && ((s0 & 3) == 0)) {
        // fast path: vectorized loads, fully unrolled 8 steps
        float4 o0 = *(const float4*)(oseq + s0);
        float4 o1 = *(const float4*)(oseq + s0 + 4);
        float4 t0 = *(const float4*)(tgt + s0);
        float4 t1 = *(const float4*)(tgt + s0 + 4);
        float o[8] = {o0.x, o0.y, o0.z, o0.w, o1.x, o1.y, o1.z, o1.w};
        float t[10];
        t[0] = (s0 >= 1) ? __ldg(tgt + s0 - 1) : 0.f;    // t_{i-2} for i=s0+1
        t[1] = t0.x; t[2] = t0.y; t[3] = t0.z; t[4] = t0.w;
        t[5] = t1.x; t[6] = t1.y; t[7] = t1.z; t[8] = t1.w;
        t[9] = (s0 + 8 < n) ? __ldg(tgt + s0 + 8) : 0.f; // t_i for i=s0+8
#pragma unroll
        for (int k = 0; k < 8; ++k) {
            const long i = s0 + 1 + k;
            float a = (i >= 2)     ? fabsf(o[k] - t[k])     : INF;
            float b =                fabsf(o[k] - t[k + 1]);
            float c = (i <= n - 1) ? fabsf(o[k] - t[k + 2]) : INF;
            step_cols(M, a, b, c);
        }
    } else {
        // generic guarded path
        for (int k = 0; k < chunk; ++k) {
            const long i = s0 + 1 + k;
            if (i > n) break;
            float o = __ldg(oseq + (i - 1));
            float a = (i >= 2)     ? fabsf(o - __ldg(tgt + (i - 2))) : INF;
            float b =                fabsf(o - __ldg(tgt + (i - 1)));
            float c = (i <= n - 1) ? fabsf(o - __ldg(tgt + i))       : INF;
            step_cols(M, a, b, c);
        }
    }

    // In-warp ordered reduce: lane 0 of each warp holds its warp product.
    warp_reduce_mat<5>(M, lane);

    __shared__ Mat swarp[NWARPS];
    if (lane == 0) swarp[warp] = M;
    __syncthreads();

    // Warp 0 finishes the block (lanes 0..NWARPS-1 lane-parallel), publishes,
    // takes a ticket, and — if last — does the final 32-matrix reduce alone.
    if (warp == 0) {
        Mat B = (lane < NWARPS) ? swarp[lane] : mp_identity();
        warp_reduce_mat<4>(B, lane);  // 16 warps -> 4 levels

        unsigned int tk = 0;
        if (lane == 0) {
#pragma unroll
            for (int q = 0; q < 9; ++q) g_bmats[blockIdx.x * 9 + q] = B.m[q];
            __threadfence();
            tk = atomicAdd(&g_ticket, 1u);
        }
        tk = __shfl_sync(0xffffffffu, tk, 0);

        if (tk == NBLOCKS - 1) {
            __threadfence();  // acquire: see all blocks' g_bmats
            Mat F;
#pragma unroll
            for (int q = 0; q < 9; ++q) F.m[q] = g_bmats[lane * 9 + q];
            warp_reduce_mat<5>(F, lane);  // 32 block-mats -> 5 levels
            if (lane == 0) {
                // v_init = (INF, 0, INF); answer = M_total[1][1]
                out[0] = F.m[4];
                g_ticket = 0;  // reset for next graph replay
            }
        }
    }
}

extern "C" void kernel_launch(void* const* d_in, const int* in_sizes, int n_in,
                              void* d_out, int out_size) {
    const float* oseq = (const float*)d_in[0];
    const float* tgt  = (const float*)d_in[1];
    const int n = in_sizes[0];

    const int P = NTHREADS * NBLOCKS;
    const int chunk = (n + P - 1) / P;

    dtw_fused<<<NBLOCKS, NTHREADS>>>(oseq, tgt, n, chunk, (float*)d_out);
}

// round 9
// speedup vs baseline: 1.0332x; 1.0332x over previous
#include <cuda_runtime.h>

// Banded DTW (Sakoe-Chiba w=1) as a min-plus (tropical) 3x3 matrix reduction,
// single fused kernel, last-block-done.
//
// Empirical model (R3/R4/R7): latency-floor bound; 128 blocks across 128 SMs
// fetch fastest; sync costs (ticket atomic, fence) are negligible; the lever
// is the in-kernel critical path length.
//
// Row recurrence (costs a=|o_i-t_{i-2}|, b=|o_i-t_{i-1}|, c=|o_i-t_i|;
// a=INF at i=1, c=INF at i=n):
//   n0 = a + min(p0,p1); n1 = b + min(n0,min(p1,p2)); n2 = c + min(n1,p2)
// Min-plus linear -> ordered reduction of 3x3 tropical matrices.
// Answer = M_total[1][1].

#define NTHREADS 128
#define NBLOCKS  128
#define NWARPS   (NTHREADS / 32)   // 4
#define MATS_PER_LANE (NBLOCKS / 32)  // 4

__device__ float g_bmats[NBLOCKS * 9];
__device__ unsigned int g_ticket = 0;

__device__ __forceinline__ float finf() { return __int_as_float(0x7f800000); }

struct Mat { float m[9]; };  // row-major

__device__ __forceinline__ Mat mp_identity() {
    const float INF = finf();
    Mat M;
    M.m[0] = 0.f; M.m[1] = INF; M.m[2] = INF;
    M.m[3] = INF; M.m[4] = 0.f; M.m[5] = INF;
    M.m[6] = INF; M.m[7] = INF; M.m[8] = 0.f;
    return M;
}

// C = L o E (E earlier, L later): C[i][j] = min_k L[i][k] + E[k][j]
__device__ __forceinline__ Mat mp_combine(const Mat& L, const Mat& E) {
    Mat C;
#pragma unroll
    for (int i = 0; i < 3; ++i) {
#pragma unroll
        for (int j = 0; j < 3; ++j) {
            float v = L.m[i * 3 + 0] + E.m[0 + j];
            v = fminf(v, L.m[i * 3 + 1] + E.m[3 + j]);
            v = fminf(v, L.m[i * 3 + 2] + E.m[6 + j]);
            C.m[i * 3 + j] = v;
        }
    }
    return C;
}

// One DTW row-step applied to all three columns of M.
__device__ __forceinline__ void step_cols(Mat& M, float a, float b, float c) {
#pragma unroll
    for (int j = 0; j < 3; ++j) {
        float p0 = M.m[0 + j], p1 = M.m[3 + j], p2 = M.m[6 + j];
        float n0 = a + fminf(p0, p1);
        float n1 = b + fminf(n0, fminf(p1, p2));
        float n2 = c + fminf(n1, p2);
        M.m[0 + j] = n0; M.m[3 + j] = n1; M.m[6 + j] = n2;
    }
}

// Order-preserving in-warp tree over LEVELS shuffle stages.
// Lane t holds segment t (ascending = later). Result lands in lane 0.
template <int LEVELS>
__device__ __forceinline__ void warp_reduce_mat(Mat& M, int lane) {
#pragma unroll
    for (int s = 1; s < (1 << LEVELS); s <<= 1) {
        Mat other;
#pragma unroll
        for (int q = 0; q < 9; ++q)
            other.m[q] = __shfl_down_sync(0xffffffffu, M.m[q], s);
        if ((lane & (2 * s - 1)) == 0) M = mp_combine(other, M);
    }
}

__global__ void __launch_bounds__(NTHREADS) dtw_fused(
    const float* __restrict__ oseq, const float* __restrict__ tgt,
    int n, int chunk, float* __restrict__ out) {
    const float INF = finf();
    const int tid = threadIdx.x;
    const int lane = tid & 31;
    const int warp = tid >> 5;
    const int gid = blockIdx.x * NTHREADS + tid;
    const int s0 = gid * chunk;  // first step handled is i = s0 + 1 (1-based)

    Mat M = mp_identity();

    if (chunk == 8 && s0 + 8 <= n && ((s0 & 3) == 0)) {
        // fast path: vectorized loads, fully unrolled 8 steps
        float4 o0 = *(const float4*)(oseq + s0);
        float4 o1 = *(const float4*)(oseq + s0 + 4);
        float4 t0 = *(const float4*)(tgt + s0);
        float4 t1 = *(const float4*)(tgt + s0 + 4);
        float o[8] = {o0.x, o0.y, o0.z, o0.w, o1.x, o1.y, o1.z, o1.w};
        float t[10];
        t[0] = (s0 >= 1) ? __ldg(tgt + s0 - 1) : 0.f;    // t_{i-2} for i=s0+1
        t[1] = t0.x; t[2] = t0.y; t[3] = t0.z; t[4] = t0.w;
        t[5] = t1.x; t[6] = t1.y; t[7] = t1.z; t[8] = t1.w;
        t[9] = (s0 + 8 < n) ? __ldg(tgt + s0 + 8) : 0.f; // t_i for i=s0+8
#pragma unroll
        for (int k = 0; k < 8; ++k) {
            const int i = s0 + 1 + k;
            float a = (i >= 2)     ? fabsf(o[k] - t[k])     : INF;
            float b =                fabsf(o[k] - t[k + 1]);
            float c = (i <= n - 1) ? fabsf(o[k] - t[k + 2]) : INF;
            step_cols(M, a, b, c);
        }
    } else {
        // generic guarded path
        for (int k = 0; k < chunk; ++k) {
            const int i = s0 + 1 + k;
            if (i > n) break;
            float o = __ldg(oseq + (i - 1));
            float a = (i >= 2)     ? fabsf(o - __ldg(tgt + (i - 2))) : INF;
            float b =                fabsf(o - __ldg(tgt + (i - 1)));
            float c = (i <= n - 1) ? fabsf(o - __ldg(tgt + i))       : INF;
            step_cols(M, a, b, c);
        }
    }

    // In-warp ordered reduce: lane 0 of each warp holds its warp product.
    warp_reduce_mat<5>(M, lane);

    __shared__ Mat swarp[NWARPS];
    if (lane == 0) swarp[warp] = M;
    __syncthreads();

    // Warp 0 finishes the block (lanes 0..NWARPS-1 lane-parallel, 2 shuffle
    // levels), publishes, takes a ticket; last block reduces all 128.
    if (warp == 0) {
        Mat B = (lane < NWARPS) ? swarp[lane] : mp_identity();
        warp_reduce_mat<2>(B, lane);  // 4 warps -> 2 levels

        unsigned int tk = 0;
        if (lane == 0) {
#pragma unroll
            for (int q = 0; q < 9; ++q)
                __stcg(&g_bmats[blockIdx.x * 9 + q], B.m[q]);
            __threadfence();
            tk = atomicAdd(&g_ticket, 1u);
        }
        tk = __shfl_sync(0xffffffffu, tk, 0);

        if (tk == NBLOCKS - 1) {
            __threadfence();  // acquire: see all blocks' g_bmats
            // Lane-parallel tail: lane folds block-mats [4l .. 4l+3]
            // (index ascending = later), then 5-level ordered tree.
            const int base = lane * MATS_PER_LANE;
            Mat F;
#pragma unroll
            for (int q = 0; q < 9; ++q) F.m[q] = __ldcg(&g_bmats[base * 9 + q]);
#pragma unroll
            for (int r = 1; r < MATS_PER_LANE; ++r) {
                Mat Nx;
#pragma unroll
                for (int q = 0; q < 9; ++q)
                    Nx.m[q] = __ldcg(&g_bmats[(base + r) * 9 + q]);
                F = mp_combine(Nx, F);  // later o earlier
            }
            warp_reduce_mat<5>(F, lane);
            if (lane == 0) {
                // v_init = (INF, 0, INF); answer = M_total[1][1]
                out[0] = F.m[4];
                g_ticket = 0;  // reset for next graph replay
            }
        }
    }
}

extern "C" void kernel_launch(void* const* d_in, const int* in_sizes, int n_in,
                              void* d_out, int out_size) {
    const float* oseq = (const float*)d_in[0];
    const float* tgt  = (const float*)d_in[1];
    const int n = in_sizes[0];

    const int P = NTHREADS * NBLOCKS;
    const int chunk = (n + P - 1) / P;

    dtw_fused<<<NBLOCKS, NTHREADS>>>(oseq, tgt, n, chunk, (float*)d_out);
}